// round 1
// baseline (speedup 1.0000x reference)
#include <cuda_runtime.h>
#include <cuda_bf16.h>
#include <limits.h>

// Sorted-segment-sum of gathered values:
//   out[s] = sum over j with seg[j]==s of cv[idx[j]]
// seg[] is sorted ascending. Empty segments must be 0 (out is poisoned).
//
// Strategy: warp-cooperative segmented scan.
//  - Each warp owns CPW consecutive 32-edge chunks (coalesced loads).
//  - Head-flag segmented inclusive scan via shuffles.
//  - One atomicAdd per segment boundary; a lane-31 carry chains partial
//    sums across chunks within the warp, so most segments cost 1 atomic.

#define CPW 16  // 32-edge chunks per warp => 512 edges per warp

__global__ void zero_out_kernel(float* __restrict__ out, int n) {
    int i = blockIdx.x * blockDim.x + threadIdx.x;
    if (i < n) out[i] = 0.0f;
}

__global__ __launch_bounds__(256, 8)
void seg_sum_kernel(const float* __restrict__ cv,
                    const int*   __restrict__ idx,
                    const int*   __restrict__ seg,
                    float*       __restrict__ out,
                    int E)
{
    const int lane = threadIdx.x & 31;
    const long long warp_id =
        (long long)blockIdx.x * (blockDim.x >> 5) + (threadIdx.x >> 5);

    long long base = warp_id * (32LL * CPW);
    if (base >= (long long)E) return;
    long long lim = base + 32LL * CPW;
    if (lim > (long long)E) lim = (long long)E;

    float carry     = 0.0f;
    int   carry_seg = -1;   // -1 = no pending carry

    for (long long p = base; p < lim; p += 32) {
        long long j  = p + lane;
        bool valid   = (j < lim);

        int   s = INT_MAX;  // sentinel: invalid lanes form their own fake segment
        float v = 0.0f;
        if (valid) {
            s = seg[j];
            v = __ldg(&cv[idx[j]]);
        }

        // head flags: lane starts a new segment
        int  s_prev = __shfl_up_sync(0xffffffffu, s, 1);
        bool head   = (lane == 0) || (s != s_prev);
        unsigned head_mask = __ballot_sync(0xffffffffu, head);

        // seg_start = highest head lane <= this lane (lane 0 is always head)
        unsigned mask_le = head_mask & (0xffffffffu >> (31 - lane));
        int seg_start = 31 - __clz(mask_le);

        // segmented inclusive scan (Hillis-Steele, clamped at seg_start)
        float x = v;
        #pragma unroll
        for (int d = 1; d < 32; d <<= 1) {
            float y = __shfl_up_sync(0xffffffffu, x, d);
            if (lane - d >= seg_start) x += y;
        }

        int s0 = __shfl_sync(0xffffffffu, s, 0);

        // merge or flush the carry from the previous chunk
        if (carry_seg == s0) {
            // previous chunk's trailing segment continues here:
            // fold carry into every lane of the first segment
            if (seg_start == 0) x += carry;
        } else if (carry_seg >= 0) {
            if (lane == 0) atomicAdd(&out[carry_seg], carry);
        }

        // a lane is a segment tail if the next lane is a head (or lane 31)
        bool tail = (lane == 31) || ((head_mask >> (lane + 1)) & 1u);
        if (tail && lane != 31 && valid) {
            atomicAdd(&out[s], x);
        }

        // lane 31's (possibly partial) segment becomes the new carry
        carry     = __shfl_sync(0xffffffffu, x, 31);
        int s31   = __shfl_sync(0xffffffffu, s, 31);
        carry_seg = (s31 == INT_MAX) ? -1 : s31;
    }

    if (carry_seg >= 0 && lane == 0) {
        atomicAdd(&out[carry_seg], carry);
    }
}

extern "C" void kernel_launch(void* const* d_in, const int* in_sizes, int n_in,
                              void* d_out, int out_size)
{
    // metadata order:
    //   d_in[0] child_val    float32  (1, M)
    //   d_in[1] flat_indices int32    (E,)
    //   d_in[2] segment_ids  int32    (E,)
    //   d_in[3] num_nodes    int32    (scalar) -- out_size already equals batch*num_nodes
    const float* cv  = (const float*)d_in[0];
    const int*   idx = (const int*)d_in[1];
    const int*   seg = (const int*)d_in[2];
    float*       out = (float*)d_out;

    const int E = in_sizes[1];
    const int N = out_size;

    // 1) zero output (empty segments must be 0; d_out is poisoned)
    {
        int threads = 256;
        int blocks  = (N + threads - 1) / threads;
        zero_out_kernel<<<blocks, threads>>>(out, N);
    }

    // 2) segmented sum
    {
        long long edges_per_warp = 32LL * CPW;
        long long n_warps  = (E + edges_per_warp - 1) / edges_per_warp;
        int warps_per_blk  = 256 / 32;
        long long n_blocks = (n_warps + warps_per_blk - 1) / warps_per_blk;
        seg_sum_kernel<<<(int)n_blocks, 256>>>(cv, idx, seg, out, E);
    }
}

// round 2
// speedup vs baseline: 1.2330x; 1.2330x over previous
#include <cuda_runtime.h>
#include <cuda_bf16.h>
#include <limits.h>

// Sorted-segment-sum of gathered values:
//   out[s] = sum over j with seg[j]==s of cv[idx[j]]
// seg[] sorted ascending. Empty segments must be 0 (out is poisoned).
//
// Fast path: each lane processes 4 consecutive edges via int4 loads
// (warp covers 128 contiguous edges, coalesced). Runs fully inside a
// thread flush directly; per-thread trailing runs are combined with a
// warp-level segmented (value,flag) scan. A lane-31 carry chains across
// the warp's iterations, so each segment costs ~1 atomicAdd total.

#define FULL 0xffffffffu
#define EDGES_PER_WARP 512   // 4 iterations x 128 edges

__global__ void zero_out_kernel(float* __restrict__ out, int n) {
    int i = blockIdx.x * blockDim.x + threadIdx.x;
    if (i < n) out[i] = 0.0f;
}

__global__ __launch_bounds__(256, 8)
void seg_sum_kernel(const float* __restrict__ cv,
                    const int*   __restrict__ idx,
                    const int*   __restrict__ seg,
                    float*       __restrict__ out,
                    int E)
{
    const int lane = threadIdx.x & 31;
    const long long warp_id =
        (long long)blockIdx.x * (blockDim.x >> 5) + (threadIdx.x >> 5);

    long long base = warp_id * (long long)EDGES_PER_WARP;
    if (base >= (long long)E) return;
    long long lim = base + EDGES_PER_WARP;
    if (lim > (long long)E) lim = (long long)E;

    float carry     = 0.0f;
    int   carry_seg = -1;   // -1 = no pending carry

    if (lim - base == EDGES_PER_WARP) {
        // ---------------- fast path: 4 iterations of 128 edges ----------------
        const int4* idx4 = (const int4*)idx;
        const int4* seg4 = (const int4*)seg;

        #pragma unroll
        for (int it = 0; it < EDGES_PER_WARP / 128; it++) {
            long long q = (base >> 2) + (long long)it * 32 + lane;  // int4 index
            int4 si = seg4[q];
            int4 ii = idx4[q];

            float v0 = __ldg(&cv[ii.x]);
            float v1 = __ldg(&cv[ii.y]);
            float v2 = __ldg(&cv[ii.z]);
            float v3 = __ldg(&cv[ii.w]);

            int   s_arr[4] = { si.x, si.y, si.z, si.w };
            float v_arr[4] = { v0, v1, v2, v3 };

            // per-thread run detection over 4 consecutive edges
            float run = v_arr[0];
            int   rs  = s_arr[0];
            const int sfirst = s_arr[0];
            float lead = 0.0f;
            bool  leadDone = false;
            #pragma unroll
            for (int i = 1; i < 4; i++) {
                if (s_arr[i] == rs) {
                    run += v_arr[i];
                } else {
                    if (!leadDone) { lead = run; leadDone = true; }
                    else           { atomicAdd(&out[rs], run); }  // interior run: complete
                    run = v_arr[i];
                    rs  = s_arr[i];
                }
            }
            const float trail   = run;   // if allsame, this is the total of all 4
            const int   slast   = rs;
            const bool  allsame = !leadDone;

            // connectivity with preceding lane / iteration carry
            int  prev_slast = __shfl_up_sync(FULL, slast, 1);
            bool connected  = (lane == 0) ? (carry_seg == sfirst)
                                          : (prev_slast == sfirst);

            // scan input: trailing-run value; fold carry in at lane 0 when
            // the whole thread is one run continuing the carry segment
            float sv = trail;
            if (lane == 0 && connected && allsame) sv += carry;
            bool f = (lane == 0) || !allsame || !connected;  // chain reset before lane

            // segmented inclusive scan: op (v1,f1)+(v2,f2) = (f2?v2:v1+v2, f1|f2)
            #pragma unroll
            for (int d = 1; d < 32; d <<= 1) {
                float    ov = __shfl_up_sync(FULL, sv, d);
                unsigned of = __shfl_up_sync(FULL, (unsigned)f, d);
                if (lane >= d) {
                    if (!f) sv += ov;
                    f = f || (of != 0);
                }
            }

            // chain-sum ending at lane-1 (completed value for segment sfirst)
            float inc_prev = __shfl_up_sync(FULL, sv, 1);
            if (lane == 0) inc_prev = carry;

            // flush this thread's leading run (complete since !allsame)
            if (!allsame) {
                float add = lead + (connected ? inc_prev : 0.0f);
                atomicAdd(&out[sfirst], add);
            }
            // lane 0 disconnected: the inter-iteration carry segment is complete
            if (lane == 0 && !connected && carry_seg >= 0) {
                atomicAdd(&out[carry_seg], carry);
            }

            // trailing-run flush: complete if the next lane doesn't continue it
            int  next_sfirst    = __shfl_down_sync(FULL, sfirst, 1);
            bool next_connected = (next_sfirst == slast);
            if (lane < 31 && !next_connected) {
                atomicAdd(&out[slast], sv);
            }

            // lane 31's chain becomes the carry
            carry     = __shfl_sync(FULL, sv, 31);
            carry_seg = __shfl_sync(FULL, slast, 31);
        }
    } else {
        // ---------------- scalar tail path (partial warp range) ----------------
        for (long long p = base; p < lim; p += 32) {
            long long j = p + lane;
            bool valid  = (j < lim);

            int   s = INT_MAX;
            float v = 0.0f;
            if (valid) {
                s = seg[j];
                v = __ldg(&cv[idx[j]]);
            }

            int  s_prev = __shfl_up_sync(FULL, s, 1);
            bool head   = (lane == 0) || (s != s_prev);
            unsigned head_mask = __ballot_sync(FULL, head);

            unsigned mask_le = head_mask & (FULL >> (31 - lane));
            int seg_start = 31 - __clz(mask_le);

            float x = v;
            #pragma unroll
            for (int d = 1; d < 32; d <<= 1) {
                float y = __shfl_up_sync(FULL, x, d);
                if (lane - d >= seg_start) x += y;
            }

            int s0 = __shfl_sync(FULL, s, 0);
            if (carry_seg == s0) {
                if (seg_start == 0) x += carry;
            } else if (carry_seg >= 0) {
                if (lane == 0) atomicAdd(&out[carry_seg], carry);
            }

            bool tail = (lane == 31) || ((head_mask >> (lane + 1)) & 1u);
            if (tail && lane != 31 && valid) {
                atomicAdd(&out[s], x);
            }

            carry   = __shfl_sync(FULL, x, 31);
            int s31 = __shfl_sync(FULL, s, 31);
            carry_seg = (s31 == INT_MAX) ? -1 : s31;
        }
    }

    if (carry_seg >= 0 && lane == 0) {
        atomicAdd(&out[carry_seg], carry);
    }
}

extern "C" void kernel_launch(void* const* d_in, const int* in_sizes, int n_in,
                              void* d_out, int out_size)
{
    const float* cv  = (const float*)d_in[0];
    const int*   idx = (const int*)d_in[1];
    const int*   seg = (const int*)d_in[2];
    float*       out = (float*)d_out;

    const int E = in_sizes[1];
    const int N = out_size;

    {
        int threads = 256;
        int blocks  = (N + threads - 1) / threads;
        zero_out_kernel<<<blocks, threads>>>(out, N);
    }
    {
        long long n_warps  = ((long long)E + EDGES_PER_WARP - 1) / EDGES_PER_WARP;
        int warps_per_blk  = 256 / 32;
        long long n_blocks = (n_warps + warps_per_blk - 1) / warps_per_blk;
        seg_sum_kernel<<<(int)n_blocks, 256>>>(cv, idx, seg, out, E);
    }
}

// round 3
// speedup vs baseline: 1.2735x; 1.0329x over previous
#include <cuda_runtime.h>
#include <cuda_bf16.h>
#include <limits.h>

// Sorted-segment-sum of gathered values:
//   out[s] = sum over j with seg[j]==s of cv[idx[j]]
// seg[] sorted ascending. Empty segments must be 0 (out is poisoned).
//
// Each lane processes 8 consecutive edges (2x int4 loads of idx/seg; warp
// covers 256 contiguous edges, coalesced). Runs fully interior to a thread
// flush directly; per-thread trailing runs are combined with a ballot-based
// clamped warp scan. A lane-31 carry chains across iterations, so each
// segment costs ~1 atomicAdd total.

#define FULL 0xffffffffu
#define EDGES_PER_WARP 1024   // 4 iterations x 256 edges

__global__ void zero_out_kernel(float4* __restrict__ out4, int n4,
                                float* __restrict__ out, int n) {
    int i = blockIdx.x * blockDim.x + threadIdx.x;
    if (i < n4) out4[i] = make_float4(0.f, 0.f, 0.f, 0.f);
    // scalar remainder
    int r = n4 * 4 + i;
    if (i < (n - n4 * 4)) out[r] = 0.0f;
}

__global__ __launch_bounds__(256)
void seg_sum_kernel(const float* __restrict__ cv,
                    const int*   __restrict__ idx,
                    const int*   __restrict__ seg,
                    float*       __restrict__ out,
                    int E)
{
    const int lane = threadIdx.x & 31;
    const long long warp_id =
        (long long)blockIdx.x * (blockDim.x >> 5) + (threadIdx.x >> 5);

    long long base = warp_id * (long long)EDGES_PER_WARP;
    if (base >= (long long)E) return;
    long long lim = base + EDGES_PER_WARP;
    if (lim > (long long)E) lim = (long long)E;

    float carry     = 0.0f;
    int   carry_seg = -1;   // -1 = no pending carry

    if (lim - base == EDGES_PER_WARP) {
        // ------------- fast path: 4 iterations of 256 edges -------------
        const int4* idx4 = (const int4*)idx;
        const int4* seg4 = (const int4*)seg;

        #pragma unroll
        for (int it = 0; it < EDGES_PER_WARP / 256; it++) {
            // each lane owns 2 consecutive int4's => 8 consecutive edges
            long long q = (base >> 2) + (long long)it * 64 + lane * 2;
            int4 sa = seg4[q];
            int4 sb = seg4[q + 1];
            int4 ia = idx4[q];
            int4 ib = idx4[q + 1];

            float v_arr[8];
            v_arr[0] = __ldg(&cv[ia.x]);
            v_arr[1] = __ldg(&cv[ia.y]);
            v_arr[2] = __ldg(&cv[ia.z]);
            v_arr[3] = __ldg(&cv[ia.w]);
            v_arr[4] = __ldg(&cv[ib.x]);
            v_arr[5] = __ldg(&cv[ib.y]);
            v_arr[6] = __ldg(&cv[ib.z]);
            v_arr[7] = __ldg(&cv[ib.w]);

            int s_arr[8] = { sa.x, sa.y, sa.z, sa.w, sb.x, sb.y, sb.z, sb.w };

            // per-thread run detection over 8 consecutive edges
            float run = v_arr[0];
            int   rs  = s_arr[0];
            const int sfirst = s_arr[0];
            float lead = 0.0f;
            bool  leadDone = false;
            #pragma unroll
            for (int i = 1; i < 8; i++) {
                if (s_arr[i] == rs) {
                    run += v_arr[i];
                } else {
                    if (!leadDone) { lead = run; leadDone = true; }
                    else           { atomicAdd(&out[rs], run); }  // interior run: complete
                    run = v_arr[i];
                    rs  = s_arr[i];
                }
            }
            const float trail   = run;     // if allsame: total of all 8
            const int   slast   = rs;
            const bool  allsame = !leadDone;

            // connectivity with preceding lane / iteration carry
            int  prev_slast = __shfl_up_sync(FULL, slast, 1);
            bool connected  = (lane == 0) ? (carry_seg == sfirst)
                                          : (prev_slast == sfirst);

            // scan input: trailing-run value; fold the carry in at lane 0 when
            // the whole thread is one run continuing the carry segment
            float sv = trail;
            if (lane == 0 && connected && allsame) sv += carry;
            bool f = (lane == 0) || !allsame || !connected;  // chain break before lane

            // ballot-based clamped inclusive scan over trailing-run chain
            unsigned head_mask = __ballot_sync(FULL, f);     // bit0 always set
            unsigned mask_le   = head_mask & (FULL >> (31 - lane));
            int seg_start = 31 - __clz(mask_le);
            #pragma unroll
            for (int d = 1; d < 32; d <<= 1) {
                float y = __shfl_up_sync(FULL, sv, d);
                if (lane - d >= seg_start) sv += y;
            }

            // chain-sum ending at lane-1 (completed prefix for segment sfirst)
            float inc_prev = __shfl_up_sync(FULL, sv, 1);
            if (lane == 0) inc_prev = carry;

            // flush this thread's leading run (complete since !allsame)
            if (!allsame) {
                float add = lead + (connected ? inc_prev : 0.0f);
                atomicAdd(&out[sfirst], add);
            }
            // lane 0 disconnected: the inter-iteration carry segment is complete
            if (lane == 0 && !connected && carry_seg >= 0) {
                atomicAdd(&out[carry_seg], carry);
            }

            // trailing-run flush: complete if the next lane doesn't continue it
            int  next_sfirst    = __shfl_down_sync(FULL, sfirst, 1);
            bool next_connected = (next_sfirst == slast);
            if (lane < 31 && !next_connected) {
                atomicAdd(&out[slast], sv);
            }

            // lane 31's chain becomes the carry
            carry     = __shfl_sync(FULL, sv, 31);
            carry_seg = __shfl_sync(FULL, slast, 31);
        }
    } else {
        // ------------- scalar tail path (partial warp range) -------------
        for (long long p = base; p < lim; p += 32) {
            long long j = p + lane;
            bool valid  = (j < lim);

            int   s = INT_MAX;
            float v = 0.0f;
            if (valid) {
                s = seg[j];
                v = __ldg(&cv[idx[j]]);
            }

            int  s_prev = __shfl_up_sync(FULL, s, 1);
            bool head   = (lane == 0) || (s != s_prev);
            unsigned head_mask = __ballot_sync(FULL, head);

            unsigned mask_le = head_mask & (FULL >> (31 - lane));
            int seg_start = 31 - __clz(mask_le);

            float x = v;
            #pragma unroll
            for (int d = 1; d < 32; d <<= 1) {
                float y = __shfl_up_sync(FULL, x, d);
                if (lane - d >= seg_start) x += y;
            }

            int s0 = __shfl_sync(FULL, s, 0);
            if (carry_seg == s0) {
                if (seg_start == 0) x += carry;
            } else if (carry_seg >= 0) {
                if (lane == 0) atomicAdd(&out[carry_seg], carry);
            }

            bool tail = (lane == 31) || ((head_mask >> (lane + 1)) & 1u);
            if (tail && lane != 31 && valid) {
                atomicAdd(&out[s], x);
            }

            carry   = __shfl_sync(FULL, x, 31);
            int s31 = __shfl_sync(FULL, s, 31);
            carry_seg = (s31 == INT_MAX) ? -1 : s31;
        }
    }

    if (carry_seg >= 0 && lane == 0) {
        atomicAdd(&out[carry_seg], carry);
    }
}

extern "C" void kernel_launch(void* const* d_in, const int* in_sizes, int n_in,
                              void* d_out, int out_size)
{
    const float* cv  = (const float*)d_in[0];
    const int*   idx = (const int*)d_in[1];
    const int*   seg = (const int*)d_in[2];
    float*       out = (float*)d_out;

    const int E = in_sizes[1];
    const int N = out_size;

    {
        int n4 = N / 4;
        int threads = 256;
        int blocks  = (n4 + threads - 1) / threads;
        if (blocks < 1) blocks = 1;
        zero_out_kernel<<<blocks, threads>>>((float4*)out, n4, out, N);
    }
    {
        long long n_warps  = ((long long)E + EDGES_PER_WARP - 1) / EDGES_PER_WARP;
        int warps_per_blk  = 256 / 32;
        long long n_blocks = (n_warps + warps_per_blk - 1) / warps_per_blk;
        seg_sum_kernel<<<(int)n_blocks, 256>>>(cv, idx, seg, out, E);
    }
}